// round 14
// baseline (speedup 1.0000x reference)
#include <cuda_runtime.h>
#include <cuda_bf16.h>
#include <cstdint>
#include <math.h>

typedef unsigned int u32;
typedef __nv_bfloat16 bf16;

// R14: TILE=128, 256 threads, warp tile 64x64 (2m x 4n), 1 CTA/SM.
// 96 HMMA per trunk chunk per warp -> HMMA issue density ~73% (was ~47%).
// Register double-buffered B (half-chunk groups). Frag-A layout as R12.
// bf16x3 trunk + 1x heads, prep_weights scratch unchanged.

#define NRF_THREADS 256
#define NRF_TILE    128
#define ESB 56        // e row stride in bf16
#define HOSTR 129     // head-out fp32 row stride

// frag arrays: u32[(ci*8 + blk)*128 + lane*4 + j], ci<16, blk<8 -> 65536 B each
#define FRAG_U32S 16384

// ---- scratch segment table (u32 offsets), identical to R10 ----
#define OFF_W0   0
#define OFF_W1   12288
#define OFF_W2   77824
#define OFF_W3   143360
#define OFF_W4   208896
#define OFF_W5H  274432
#define OFF_W5E  339968
#define OFF_W6   352256
#define OFF_W7   417792
#define OFF_WCH  450560
#define OFF_WCE  466944
#define SCR_TOTAL 468992
#define PREP_ELEMS 130048

__device__ __align__(16) u32 g_wscr[SCR_TOTAL];

__device__ __forceinline__ void mma16(float* d, const u32* a, const u32* b) {
    asm volatile(
        "mma.sync.aligned.m16n8k16.row.col.f32.bf16.bf16.f32 "
        "{%0,%1,%2,%3}, {%4,%5,%6,%7}, {%8,%9}, {%0,%1,%2,%3};\n"
        : "+f"(d[0]), "+f"(d[1]), "+f"(d[2]), "+f"(d[3])
        : "r"(a[0]), "r"(a[1]), "r"(a[2]), "r"(a[3]),
          "r"(b[0]), "r"(b[1]));
}

__device__ __forceinline__ u32 pack2(bf16 a, bf16 b) {
    __nv_bfloat162 p;
    p.x = a; p.y = b;
    return *reinterpret_cast<u32*>(&p);
}

__device__ __forceinline__ void bsplit(float v, bf16& h, bf16& l) {
    h = __float2bfloat16_rn(v);
    l = __float2bfloat16_rn(v - __bfloat162float(h));
}

__device__ __forceinline__ float bf_lo(u32 u) {
    return __bfloat162float(*reinterpret_cast<const bf16*>(&u));
}
__device__ __forceinline__ float bf_hi(u32 u) {
    return __bfloat162float(*(reinterpret_cast<const bf16*>(&u) + 1));
}

// =====================================================================
// Pre-pass: build B-fragment scratch (identical to R10).
// =====================================================================
#define NSEG 11
__global__ void prep_weights(
    const float* __restrict__ W0, const float* __restrict__ W1,
    const float* __restrict__ W2, const float* __restrict__ W3,
    const float* __restrict__ W4, const float* __restrict__ W5,
    const float* __restrict__ W6, const float* __restrict__ W7,
    const float* __restrict__ Wc)
{
    const int nch[NSEG] = {3,16,16,16,16,16,3,16,16,16,2};
    const int ntl[NSEG] = {32,32,32,32,32,32,32,32,32,16,16};
    const int is3[NSEG] = {1,1,1,1,1,1,1,1,0,0,0};
    const int ldw[NSEG] = {256,256,256,256,256,256,256,256,257,128,128};
    const int cof[NSEG] = {0,0,0,0,0,0,0,0,1,0,0};
    const int kwb[NSEG] = {0,0,0,0,0,0,256,0,0,0,256};
    const int kre[NSEG] = {39,256,256,256,256,256,39,256,256,256,27};
    const int off[NSEG] = {OFF_W0,OFF_W1,OFF_W2,OFF_W3,OFF_W4,OFF_W5H,
                           OFF_W5E,OFF_W6,OFF_W7,OFF_WCH,OFF_WCE};
    const float* Wp[NSEG] = {W0,W1,W2,W3,W4,W5,W5,W6,W7,Wc,Wc};

    int gid = blockIdx.x * blockDim.x + threadIdx.x;
    if (gid >= PREP_ELEMS) return;

    int seg = 0, acc = 0;
    for (int s = 0; s < NSEG; s++) {
        const int cnt = nch[s] * ntl[s] * 32;
        if (gid < acc + cnt) { seg = s; break; }
        acc += cnt;
    }
    int rem = gid - acc;
    const int lane  = rem & 31;  rem >>= 5;
    const int ntile = rem % ntl[seg];
    const int ci    = rem / ntl[seg];
    const int tg = lane >> 2, tq = lane & 3;
    const int col = cof[seg] + ntile * 8 + tg;
    const int k0  = ci * 16;
    const float* W = Wp[seg];
    const int ld = ldw[seg], kb = kwb[seg], KR = kre[seg];

    const float wA = (k0 + 2*tq     < KR) ? W[(size_t)(kb + k0 + 2*tq    ) * ld + col] : 0.f;
    const float wB = (k0 + 2*tq + 1 < KR) ? W[(size_t)(kb + k0 + 2*tq + 1) * ld + col] : 0.f;
    const float wC = (k0 + 8 + 2*tq     < KR) ? W[(size_t)(kb + k0 + 8 + 2*tq    ) * ld + col] : 0.f;
    const float wD = (k0 + 8 + 2*tq + 1 < KR) ? W[(size_t)(kb + k0 + 8 + 2*tq + 1) * ld + col] : 0.f;
    bf16 hA,lA,hB,lB,hC,lC,hD,lD;
    bsplit(wA,hA,lA); bsplit(wB,hB,lB); bsplit(wC,hC,lC); bsplit(wD,hD,lD);

    if (is3[seg]) {
        u32* p = g_wscr + off[seg] + ci * (ntl[seg] * 128) + ntile * 128 + lane * 4;
        p[0] = pack2(hA,hB); p[1] = pack2(hC,hD);
        p[2] = pack2(lA,lB); p[3] = pack2(lC,lD);
    } else {
        u32* p = g_wscr + off[seg] + ci * (ntl[seg] * 64) + ntile * 64 + lane * 2;
        p[0] = pack2(hA,hB); p[1] = pack2(hC,hD);
    }
}

// frag uint4 index for (ci, row-block) + lane   (blk = mg*4 + mt, 8 blocks)
__device__ __forceinline__ int frag_u4(int ci, int blk, int lane) {
    return (ci * 8 + blk) * 32 + lane;
}

// ---- compute one B-pair-group (2 pairs) for bf16x3, mt=4 ----
__device__ __forceinline__ void do_group3x(
    float acc[4][8][4], const uint4* G, int gp0,
    const u32 ah[4][4], const u32 al[4][4])
{
    #pragma unroll
    for (int p = 0; p < 2; p++) {
        const u32 bhA[2] = {G[2*p].x,   G[2*p].y};
        const u32 blA[2] = {G[2*p].z,   G[2*p].w};
        const u32 bhB[2] = {G[2*p+1].x, G[2*p+1].y};
        const u32 blB[2] = {G[2*p+1].z, G[2*p+1].w};
        const int na = 2 * (gp0 + p), nb = na + 1;
        #pragma unroll
        for (int mt = 0; mt < 4; mt++) mma16(acc[mt][na], al[mt], bhA);
        #pragma unroll
        for (int mt = 0; mt < 4; mt++) mma16(acc[mt][nb], al[mt], bhB);
        #pragma unroll
        for (int mt = 0; mt < 4; mt++) mma16(acc[mt][na], ah[mt], blA);
        #pragma unroll
        for (int mt = 0; mt < 4; mt++) mma16(acc[mt][nb], ah[mt], blB);
        #pragma unroll
        for (int mt = 0; mt < 4; mt++) mma16(acc[mt][na], ah[mt], bhA);
        #pragma unroll
        for (int mt = 0; mt < 4; mt++) mma16(acc[mt][nb], ah[mt], bhB);
    }
}

// =====================================================================
// bf16x3, A from FRAG layout, register double-buffered B (half-chunks).
// nch fixed at 16 for all frag trunk layers.
// =====================================================================
__device__ __forceinline__ void accum3x_frag(
    float acc[4][8][4], const u32* __restrict__ segp,
    const uint4* __restrict__ fhi, const uint4* __restrict__ flo,
    int mg, int n0, int lane)
{
    const uint4* wb = reinterpret_cast<const uint4*>(segp) + (n0 >> 3) * 32 + lane;
    uint4 G0[4], G1[4];
    #pragma unroll
    for (int j = 0; j < 4; j++) G0[j] = __ldg(wb + j * 32);

    #pragma unroll 1
    for (int ci = 0; ci < 16; ci++) {
        const uint4* pc = wb + ci * 1024;
        // A fragments for this chunk (8 x LDS.128)
        u32 ah[4][4], al[4][4];
        #pragma unroll
        for (int mt = 0; mt < 4; mt++) {
            const uint4 AH = fhi[frag_u4(ci, mg * 4 + mt, lane)];
            const uint4 AL = flo[frag_u4(ci, mg * 4 + mt, lane)];
            ah[mt][0] = AH.x; ah[mt][1] = AH.y; ah[mt][2] = AH.z; ah[mt][3] = AH.w;
            al[mt][0] = AL.x; al[mt][1] = AL.y; al[mt][2] = AL.z; al[mt][3] = AL.w;
        }
        // prefetch half 1 of this chunk, then compute half 0
        #pragma unroll
        for (int j = 0; j < 4; j++) G1[j] = __ldg(pc + 128 + j * 32);
        do_group3x(acc, G0, 0, ah, al);
        // prefetch half 0 of next chunk, then compute half 1
        if (ci < 15) {
            #pragma unroll
            for (int j = 0; j < 4; j++) G0[j] = __ldg(pc + 1024 + j * 32);
        }
        do_group3x(acc, G1, 2, ah, al);
    }
}

// ---- bf16x3, A from LINEAR layout (e paths: L0, L5e), mt=4 ----
__device__ __forceinline__ void accum3x_lin(
    float acc[4][8][4], const u32* __restrict__ segp, int nch,
    const bf16* __restrict__ src_hi, const bf16* __restrict__ src_lo,
    int sstr, int mbase, int n0, int tg, int tq, int lane)
{
    const uint4* wb = reinterpret_cast<const uint4*>(segp) + (n0 >> 3) * 32 + lane;
    for (int ci = 0; ci < nch; ci++) {
        const uint4* pc = wb + ci * 1024;
        const int k0 = ci * 16;
        u32 ah[4][4], al[4][4];
        #pragma unroll
        for (int mt = 0; mt < 4; mt++) {
            const int r = mbase + mt * 16 + tg;
            const bf16* ph = src_hi + r * sstr + k0 + 2 * tq;
            const bf16* pl = src_lo + r * sstr + k0 + 2 * tq;
            ah[mt][0] = *(const u32*)(ph);
            ah[mt][1] = *(const u32*)(ph + 8 * sstr);
            ah[mt][2] = *(const u32*)(ph + 8);
            ah[mt][3] = *(const u32*)(ph + 8 * sstr + 8);
            al[mt][0] = *(const u32*)(pl);
            al[mt][1] = *(const u32*)(pl + 8 * sstr);
            al[mt][2] = *(const u32*)(pl + 8);
            al[mt][3] = *(const u32*)(pl + 8 * sstr + 8);
        }
        uint4 G[4];
        #pragma unroll
        for (int j = 0; j < 4; j++) G[j] = __ldg(pc + j * 32);
        do_group3x(acc, G, 0, ah, al);
        #pragma unroll
        for (int j = 0; j < 4; j++) G[j] = __ldg(pc + 128 + j * 32);
        do_group3x(acc, G, 2, ah, al);
    }
}

// ---- single-pass bf16, 256 cols, A from frag-hi (L7), half pipeline ----
__device__ __forceinline__ void accum1x_frag256(
    float acc[4][8][4], const u32* __restrict__ segp,
    const uint4* __restrict__ fhi, int mg, int n0, int lane)
{
    const uint2* wb = reinterpret_cast<const uint2*>(segp) + (n0 >> 3) * 32 + lane;
    uint2 G0[4], G1[4];
    #pragma unroll
    for (int j = 0; j < 4; j++) G0[j] = __ldg(wb + j * 32);

    #pragma unroll 1
    for (int ci = 0; ci < 16; ci++) {
        const uint2* pc = wb + ci * 1024;
        u32 ah[4][4];
        #pragma unroll
        for (int mt = 0; mt < 4; mt++) {
            const uint4 AH = fhi[frag_u4(ci, mg * 4 + mt, lane)];
            ah[mt][0] = AH.x; ah[mt][1] = AH.y; ah[mt][2] = AH.z; ah[mt][3] = AH.w;
        }
        #pragma unroll
        for (int j = 0; j < 4; j++) G1[j] = __ldg(pc + 128 + j * 32);
        #pragma unroll
        for (int p = 0; p < 2; p++) {
            const u32 bA[2] = {G0[2*p].x, G0[2*p].y};
            const u32 bB[2] = {G0[2*p+1].x, G0[2*p+1].y};
            #pragma unroll
            for (int mt = 0; mt < 4; mt++) mma16(acc[mt][2*p],   ah[mt], bA);
            #pragma unroll
            for (int mt = 0; mt < 4; mt++) mma16(acc[mt][2*p+1], ah[mt], bB);
        }
        if (ci < 15) {
            #pragma unroll
            for (int j = 0; j < 4; j++) G0[j] = __ldg(pc + 1024 + j * 32);
        }
        #pragma unroll
        for (int p = 0; p < 2; p++) {
            const u32 bA[2] = {G1[2*p].x, G1[2*p].y};
            const u32 bB[2] = {G1[2*p+1].x, G1[2*p+1].y};
            #pragma unroll
            for (int mt = 0; mt < 4; mt++) mma16(acc[mt][4+2*p],   ah[mt], bA);
            #pragma unroll
            for (int mt = 0; mt < 4; mt++) mma16(acc[mt][4+2*p+1], ah[mt], bB);
        }
    }
}

// ---- single-pass bf16, 128 cols, A from frag-hi (head h-part) ----
__device__ __forceinline__ void accum1x_frag128(
    float acc[4][4][4], const u32* __restrict__ segp, int nch,
    const uint4* __restrict__ fhi, int mg, int n0, int lane)
{
    const uint2* wb = reinterpret_cast<const uint2*>(segp) + (n0 >> 3) * 32 + lane;
    for (int ci = 0; ci < nch; ci++) {
        const uint2* pc = wb + ci * 512;
        u32 ah[4][4];
        #pragma unroll
        for (int mt = 0; mt < 4; mt++) {
            const uint4 AH = fhi[frag_u4(ci, mg * 4 + mt, lane)];
            ah[mt][0] = AH.x; ah[mt][1] = AH.y; ah[mt][2] = AH.z; ah[mt][3] = AH.w;
        }
        #pragma unroll
        for (int np = 0; np < 2; np++) {
            const uint2 Ba = __ldg(pc + (2 * np)     * 32);
            const uint2 Bb = __ldg(pc + (2 * np + 1) * 32);
            const u32 bA[2] = {Ba.x, Ba.y};
            const u32 bB[2] = {Bb.x, Bb.y};
            #pragma unroll
            for (int mt = 0; mt < 4; mt++) mma16(acc[mt][2*np],   ah[mt], bA);
            #pragma unroll
            for (int mt = 0; mt < 4; mt++) mma16(acc[mt][2*np+1], ah[mt], bB);
        }
    }
}

// ---- single-pass bf16, 128 cols, A from LINEAR (head d-part) ----
__device__ __forceinline__ void accum1x_lin128(
    float acc[4][4][4], const u32* __restrict__ segp, int nch,
    const bf16* __restrict__ src_hi, int sstr,
    int mbase, int n0, int tg, int tq, int lane)
{
    const uint2* wb = reinterpret_cast<const uint2*>(segp) + (n0 >> 3) * 32 + lane;
    for (int ci = 0; ci < nch; ci++) {
        const uint2* pc = wb + ci * 512;
        const int k0 = ci * 16;
        u32 ah[4][4];
        #pragma unroll
        for (int mt = 0; mt < 4; mt++) {
            const int r = mbase + mt * 16 + tg;
            const bf16* ph = src_hi + r * sstr + k0 + 2 * tq;
            ah[mt][0] = *(const u32*)(ph);
            ah[mt][1] = *(const u32*)(ph + 8 * sstr);
            ah[mt][2] = *(const u32*)(ph + 8);
            ah[mt][3] = *(const u32*)(ph + 8 * sstr + 8);
        }
        #pragma unroll
        for (int np = 0; np < 2; np++) {
            const uint2 Ba = __ldg(pc + (2 * np)     * 32);
            const uint2 Bb = __ldg(pc + (2 * np + 1) * 32);
            const u32 bA[2] = {Ba.x, Ba.y};
            const u32 bB[2] = {Bb.x, Bb.y};
            #pragma unroll
            for (int mt = 0; mt < 4; mt++) mma16(acc[mt][2*np],   ah[mt], bA);
            #pragma unroll
            for (int mt = 0; mt < 4; mt++) mma16(acc[mt][2*np+1], ah[mt], bB);
        }
    }
}

// ---- Trunk epilogue: bias + optional ReLU, write FRAG hi(+lo) ----
__device__ __forceinline__ void epilogue_frag(
    float acc[4][8][4], const float* __restrict__ bg, int co,
    u32* __restrict__ fhi, u32* __restrict__ flo, bool relu, bool write_lo,
    int mg, int wq, int n0, int tq, int lane)
{
    __syncthreads();
    #pragma unroll
    for (int nt = 0; nt < 8; nt++) {
        const int c = n0 + nt * 8 + 2 * tq;
        const float b0v = bg[co + c];
        const float b1v = bg[co + c + 1];
        const int ci = wq * 4 + (nt >> 1);
        #pragma unroll
        for (int mt = 0; mt < 4; mt++) {
            float v0 = acc[mt][nt][0] + b0v;
            float v1 = acc[mt][nt][1] + b1v;
            float v2 = acc[mt][nt][2] + b0v;
            float v3 = acc[mt][nt][3] + b1v;
            if (relu) {
                v0 = fmaxf(v0, 0.f); v1 = fmaxf(v1, 0.f);
                v2 = fmaxf(v2, 0.f); v3 = fmaxf(v3, 0.f);
            }
            const int ub = ((ci * 8 + mg * 4 + mt) * 128) + lane * 4 + (nt & 1) * 2;
            bf16 h0, l0, h1, l1, h2, l2, h3, l3;
            bsplit(v0, h0, l0); bsplit(v1, h1, l1);
            bsplit(v2, h2, l2); bsplit(v3, h3, l3);
            fhi[ub + 0] = pack2(h0, h1);
            fhi[ub + 1] = pack2(h2, h3);
            if (write_lo) {
                flo[ub + 0] = pack2(l0, l1);
                flo[ub + 1] = pack2(l2, l3);
            }
        }
    }
    __syncthreads();
}

// ---- Head epilogue: bias + ReLU, write fp32 LINEAR (stride HOSTR) ----
__device__ __forceinline__ void epilogue_head(
    float acc[4][4][4], const float* __restrict__ bg,
    float* __restrict__ hout, int mbase, int n0, int tg, int tq)
{
    __syncthreads();
    #pragma unroll
    for (int nt = 0; nt < 4; nt++) {
        const int c = n0 + nt * 8 + 2 * tq;
        const float b0v = bg[c];
        const float b1v = bg[c + 1];
        #pragma unroll
        for (int mt = 0; mt < 4; mt++) {
            const int r = mbase + mt * 16 + tg;
            hout[r * HOSTR + c]           = fmaxf(acc[mt][nt][0] + b0v, 0.f);
            hout[r * HOSTR + c + 1]       = fmaxf(acc[mt][nt][1] + b1v, 0.f);
            hout[(r + 8) * HOSTR + c]     = fmaxf(acc[mt][nt][2] + b0v, 0.f);
            hout[(r + 8) * HOSTR + c + 1] = fmaxf(acc[mt][nt][3] + b1v, 0.f);
        }
    }
    __syncthreads();
}

__device__ __forceinline__ void zero_acc(float acc[4][8][4]) {
    #pragma unroll
    for (int i = 0; i < 4; i++)
        #pragma unroll
        for (int j = 0; j < 8; j++)
            #pragma unroll
            for (int k = 0; k < 4; k++) acc[i][j][k] = 0.f;
}

__global__ void __launch_bounds__(NRF_THREADS, 1) nerf_tc_kernel(
    const float* __restrict__ pts, const float* __restrict__ dirs,
    const float* __restrict__ b0, const float* __restrict__ b1,
    const float* __restrict__ b2, const float* __restrict__ b3,
    const float* __restrict__ b4, const float* __restrict__ b5,
    const float* __restrict__ b6, const float* __restrict__ b7,
    const float* __restrict__ W7, const float* __restrict__ bc,
    const float* __restrict__ Wo, const float* __restrict__ bo,
    float* __restrict__ out_color, float* __restrict__ out_sigma, int P)
{
    extern __shared__ char smc[];
    u32*  fhi  = (u32*)smc;                          // 65536 B
    u32*  flo  = fhi + FRAG_U32S;                    // 66048 B (union with hout)
    float* hout = (float*)flo;                       // 128*129*4 = 66048 B
    bf16* e_hi = (bf16*)(smc + 65536 + 66048);       // [128][ESB] = 14336 B
    bf16* e_lo = e_hi + NRF_TILE * ESB;              // 14336 B

    const int tid  = threadIdx.x;
    const int warp = tid >> 5;
    const int lane = tid & 31;
    const int tg = lane >> 2;
    const int tq = lane & 3;
    const int mg = warp >> 2;              // 2 m-groups of 64 rows
    const int wq = warp & 3;               // 4 n-quads
    const int mbase  = mg * 64;
    const int n0_256 = wq * 64;
    const int n0_128 = wq * 32;
    const int base = blockIdx.x * NRF_TILE;
    const uint4* fhi4 = reinterpret_cast<const uint4*>(fhi);
    const uint4* flo4 = reinterpret_cast<const uint4*>(flo);

    // ---- xyz harmonic embedding, linear pre-split hi/lo ----
    if (tid < NRF_TILE) {
        const int n = base + tid;
        const float x = pts[n * 3 + 0];
        const float y = pts[n * 3 + 1];
        const float z = pts[n * 3 + 2];
        bf16* eh = e_hi + tid * ESB;
        bf16* el = e_lo + tid * ESB;
        #pragma unroll
        for (int h = 0; h < 6; h++) {
            const float f = (float)(1 << h);
            float sx, cx, sy, cy, sz, cz;
            sincosf(x * f, &sx, &cx);
            sincosf(y * f, &sy, &cy);
            sincosf(z * f, &sz, &cz);
            bf16 hh, ll;
            bsplit(sx, hh, ll); eh[0  + h] = hh; el[0  + h] = ll;
            bsplit(sy, hh, ll); eh[6  + h] = hh; el[6  + h] = ll;
            bsplit(sz, hh, ll); eh[12 + h] = hh; el[12 + h] = ll;
            bsplit(cx, hh, ll); eh[18 + h] = hh; el[18 + h] = ll;
            bsplit(cy, hh, ll); eh[24 + h] = hh; el[24 + h] = ll;
            bsplit(cz, hh, ll); eh[30 + h] = hh; el[30 + h] = ll;
        }
        bf16 hh, ll;
        bsplit(x, hh, ll); eh[36] = hh; el[36] = ll;
        bsplit(y, hh, ll); eh[37] = hh; el[37] = ll;
        bsplit(z, hh, ll); eh[38] = hh; el[38] = ll;
        const bf16 zb = __float2bfloat16_rn(0.f);
        #pragma unroll
        for (int c = 39; c < 48; c++) { eh[c] = zb; el[c] = zb; }
    }
    __syncthreads();

    float acc[4][8][4];

    // ---- L0: e(39) -> 256, ReLU (linear A, 3 chunks) ----
    zero_acc(acc);
    accum3x_lin(acc, g_wscr + OFF_W0, 3, e_hi, e_lo, ESB, mbase, n0_256, tg, tq, lane);
    epilogue_frag(acc, b0, 0, fhi, flo, true, true, mg, wq, n0_256, tq, lane);

    // ---- L1..L4 (frag A) ----
    {
        const u32* segs[4] = {g_wscr + OFF_W1, g_wscr + OFF_W2,
                              g_wscr + OFF_W3, g_wscr + OFF_W4};
        const float* bs[4] = {b1, b2, b3, b4};
        #pragma unroll 1
        for (int l = 0; l < 4; l++) {
            zero_acc(acc);
            accum3x_frag(acc, segs[l], fhi4, flo4, mg, n0_256, lane);
            epilogue_frag(acc, bs[l], 0, fhi, flo, true, true, mg, wq, n0_256, tq, lane);
        }
    }

    // ---- L5: [h(frag), e(linear)] ----
    zero_acc(acc);
    accum3x_frag(acc, g_wscr + OFF_W5H, fhi4, flo4, mg, n0_256, lane);
    accum3x_lin(acc, g_wscr + OFF_W5E, 3, e_hi, e_lo, ESB, mbase, n0_256, tg, tq, lane);
    epilogue_frag(acc, b5, 0, fhi, flo, true, true, mg, wq, n0_256, tq, lane);

    // ---- L6 (frag A) ----
    zero_acc(acc);
    accum3x_frag(acc, g_wscr + OFF_W6, fhi4, flo4, mg, n0_256, lane);
    epilogue_frag(acc, b6, 0, fhi, flo, true, true, mg, wq, n0_256, tq, lane);

    // ---- Sigma: fp32 dot over h6 read from frag layout ----
    if (tid < NRF_TILE) {
        const int row = tid;
        const int blk = row >> 4;
        const int shseg = (row >> 3) & 1, stg = row & 7;
        float s = b7[0];
        #pragma unroll 4
        for (int k = 0; k < 256; k += 2) {
            const int cp = k >> 1;
            const int ci = cp >> 3, cq = cp & 7;
            const int half = cq >> 2, tqd = cq & 3;
            const int idx = (ci * 8 + blk) * 128
                          + (stg * 4 + tqd) * 4 + half * 2 + shseg;
            const u32 uh = fhi[idx];
            const u32 ul = flo[idx];
            s = fmaf(bf_lo(uh) + bf_lo(ul), W7[(size_t)k * 257], s);
            s = fmaf(bf_hi(uh) + bf_hi(ul), W7[(size_t)(k + 1) * 257], s);
        }
        out_sigma[base + tid] = fmaxf(s, 0.f);
    }

    // ---- L7 cols 1..256 (1x, frag-hi A; output hi-only frags) ----
    zero_acc(acc);
    accum1x_frag256(acc, g_wscr + OFF_W7, fhi4, mg, n0_256, lane);
    epilogue_frag(acc, b7, 1, fhi, flo, false, false, mg, wq, n0_256, tq, lane);

    // ---- dir harmonic embedding into e_hi (linear) ----
    if (tid < NRF_TILE) {
        const int n = base + tid;
        const int r = n / P;
        const float dx = dirs[r * 3 + 0];
        const float dy = dirs[r * 3 + 1];
        const float dz = dirs[r * 3 + 2];
        bf16* eh = e_hi + tid * ESB;
        #pragma unroll
        for (int h = 0; h < 4; h++) {
            const float f = (float)(1 << h);
            float sx, cx, sy, cy, sz, cz;
            sincosf(dx * f, &sx, &cx);
            sincosf(dy * f, &sy, &cy);
            sincosf(dz * f, &sz, &cz);
            eh[0  + h] = __float2bfloat16_rn(sx);
            eh[4  + h] = __float2bfloat16_rn(sy);
            eh[8  + h] = __float2bfloat16_rn(sz);
            eh[12 + h] = __float2bfloat16_rn(cx);
            eh[16 + h] = __float2bfloat16_rn(cy);
            eh[20 + h] = __float2bfloat16_rn(cz);
        }
        eh[24] = __float2bfloat16_rn(dx);
        eh[25] = __float2bfloat16_rn(dy);
        eh[26] = __float2bfloat16_rn(dz);
        const bf16 zb = __float2bfloat16_rn(0.f);
        #pragma unroll
        for (int c = 27; c < 32; c++) eh[c] = zb;
    }
    __syncthreads();

    // ---- Color head: [h7(frag-hi), d(linear)] -> 128, ReLU, fp32 out ----
    {
        float acc2[4][4][4];
        #pragma unroll
        for (int i = 0; i < 4; i++)
            #pragma unroll
            for (int j = 0; j < 4; j++)
                #pragma unroll
                for (int k = 0; k < 4; k++) acc2[i][j][k] = 0.f;
        accum1x_frag128(acc2, g_wscr + OFF_WCH, 16, fhi4, mg, n0_128, lane);
        accum1x_lin128(acc2, g_wscr + OFF_WCE, 2, e_hi, ESB, mbase, n0_128, tg, tq, lane);
        epilogue_head(acc2, bc, hout, mbase, n0_128, tg, tq);
    }

    // ---- Output: sigmoid(hout @ Wo + bo), 384 pairs (grid-stride) ----
    for (int idx = tid; idx < NRF_TILE * 3; idx += NRF_THREADS) {
        const int p = idx / 3;
        const int c = idx - p * 3;
        float s = bo[c];
        const float* hp = hout + p * HOSTR;
        #pragma unroll 4
        for (int k = 0; k < 128; k++)
            s = fmaf(hp[k], Wo[k * 3 + c], s);
        out_color[(base + p) * 3 + c] = 1.f / (1.f + expf(-s));
    }
}

extern "C" void kernel_launch(void* const* d_in, const int* in_sizes, int n_in,
                              void* d_out, int out_size)
{
    const float* pts  = (const float*)d_in[0];
    const float* dirs = (const float*)d_in[1];
    const float* W0 = (const float*)d_in[2];   const float* b0 = (const float*)d_in[3];
    const float* W1 = (const float*)d_in[4];   const float* b1 = (const float*)d_in[5];
    const float* W2 = (const float*)d_in[6];   const float* b2 = (const float*)d_in[7];
    const float* W3 = (const float*)d_in[8];   const float* b3 = (const float*)d_in[9];
    const float* W4 = (const float*)d_in[10];  const float* b4 = (const float*)d_in[11];
    const float* W5 = (const float*)d_in[12];  const float* b5 = (const float*)d_in[13];
    const float* W6 = (const float*)d_in[14];  const float* b6 = (const float*)d_in[15];
    const float* W7 = (const float*)d_in[16];  const float* b7 = (const float*)d_in[17];
    const float* Wc = (const float*)d_in[18];  const float* bc = (const float*)d_in[19];
    const float* Wo = (const float*)d_in[20];  const float* bo = (const float*)d_in[21];

    const int N = in_sizes[0] / 3;        // 131072 points
    const int R = in_sizes[1] / 3;        // 2048 rays
    const int P = N / R;                  // 64 samples per ray

    float* out_color = (float*)d_out;               // [N,3] first (tuple order)
    float* out_sigma = out_color + (size_t)N * 3;   // [N,1] after

    prep_weights<<<(PREP_ELEMS + 255) / 256, 256>>>(
        W0, W1, W2, W3, W4, W5, W6, W7, Wc);

    // smem: fhi 65536 + union(flo/hout) 66048 + e_hi 14336 + e_lo 14336
    const int smem_bytes = 65536 + 66048 + 14336 + 14336;
    cudaFuncSetAttribute(nerf_tc_kernel,
                         cudaFuncAttributeMaxDynamicSharedMemorySize, smem_bytes);

    nerf_tc_kernel<<<N / NRF_TILE, NRF_THREADS, smem_bytes>>>(
        pts, dirs,
        b0, b1, b2, b3, b4, b5, b6, b7,
        W7, bc, Wo, bo,
        out_color, out_sigma, P);
}

// round 15
// speedup vs baseline: 1.2144x; 1.2144x over previous
#include <cuda_runtime.h>
#include <cuda_bf16.h>
#include <cstdint>
#include <math.h>

typedef unsigned int u32;
typedef __nv_bfloat16 bf16;

// R15: R12 champion + per-mg-group NAMED barriers on trunk epilogues
// (L0..L5): each half of the CTA (4 warps) syncs independently -> 4
// desynchronized epilogue streams per SM (2 CTAs x 2 mg-groups).
// L6/L7/head keep full barriers (sigma + output cross the mg boundary).

#define NRF_THREADS 256
#define NRF_TILE    64
#define ESB 56        // e row stride in bf16
#define HOSTR 129     // head-out fp32 row stride (conflict-free)

#define FRAG_U32S 8192

// ---- scratch segment table (u32 offsets), identical to R10 ----
#define OFF_W0   0
#define OFF_W1   12288
#define OFF_W2   77824
#define OFF_W3   143360
#define OFF_W4   208896
#define OFF_W5H  274432
#define OFF_W5E  339968
#define OFF_W6   352256
#define OFF_W7   417792
#define OFF_WCH  450560
#define OFF_WCE  466944
#define SCR_TOTAL 468992
#define PREP_ELEMS 130048

__device__ __align__(16) u32 g_wscr[SCR_TOTAL];

__device__ __forceinline__ void mma16(float* d, const u32* a, const u32* b) {
    asm volatile(
        "mma.sync.aligned.m16n8k16.row.col.f32.bf16.bf16.f32 "
        "{%0,%1,%2,%3}, {%4,%5,%6,%7}, {%8,%9}, {%0,%1,%2,%3};\n"
        : "+f"(d[0]), "+f"(d[1]), "+f"(d[2]), "+f"(d[3])
        : "r"(a[0]), "r"(a[1]), "r"(a[2]), "r"(a[3]),
          "r"(b[0]), "r"(b[1]));
}

__device__ __forceinline__ void barrier_sync(int sync_id) {
    if (sync_id < 0) {
        __syncthreads();
    } else {
        asm volatile("bar.sync %0, %1;" :: "r"(sync_id), "r"(128) : "memory");
    }
}

__device__ __forceinline__ u32 pack2(bf16 a, bf16 b) {
    __nv_bfloat162 p;
    p.x = a; p.y = b;
    return *reinterpret_cast<u32*>(&p);
}

__device__ __forceinline__ void bsplit(float v, bf16& h, bf16& l) {
    h = __float2bfloat16_rn(v);
    l = __float2bfloat16_rn(v - __bfloat162float(h));
}

__device__ __forceinline__ float bf_lo(u32 u) {
    return __bfloat162float(*reinterpret_cast<const bf16*>(&u));
}
__device__ __forceinline__ float bf_hi(u32 u) {
    return __bfloat162float(*(reinterpret_cast<const bf16*>(&u) + 1));
}

// =====================================================================
// Pre-pass: build B-fragment scratch (identical to R10).
// =====================================================================
#define NSEG 11
__global__ void prep_weights(
    const float* __restrict__ W0, const float* __restrict__ W1,
    const float* __restrict__ W2, const float* __restrict__ W3,
    const float* __restrict__ W4, const float* __restrict__ W5,
    const float* __restrict__ W6, const float* __restrict__ W7,
    const float* __restrict__ Wc)
{
    const int nch[NSEG] = {3,16,16,16,16,16,3,16,16,16,2};
    const int ntl[NSEG] = {32,32,32,32,32,32,32,32,32,16,16};
    const int is3[NSEG] = {1,1,1,1,1,1,1,1,0,0,0};
    const int ldw[NSEG] = {256,256,256,256,256,256,256,256,257,128,128};
    const int cof[NSEG] = {0,0,0,0,0,0,0,0,1,0,0};
    const int kwb[NSEG] = {0,0,0,0,0,0,256,0,0,0,256};
    const int kre[NSEG] = {39,256,256,256,256,256,39,256,256,256,27};
    const int off[NSEG] = {OFF_W0,OFF_W1,OFF_W2,OFF_W3,OFF_W4,OFF_W5H,
                           OFF_W5E,OFF_W6,OFF_W7,OFF_WCH,OFF_WCE};
    const float* Wp[NSEG] = {W0,W1,W2,W3,W4,W5,W5,W6,W7,Wc,Wc};

    int gid = blockIdx.x * blockDim.x + threadIdx.x;
    if (gid >= PREP_ELEMS) return;

    int seg = 0, acc = 0;
    for (int s = 0; s < NSEG; s++) {
        const int cnt = nch[s] * ntl[s] * 32;
        if (gid < acc + cnt) { seg = s; break; }
        acc += cnt;
    }
    int rem = gid - acc;
    const int lane  = rem & 31;  rem >>= 5;
    const int ntile = rem % ntl[seg];
    const int ci    = rem / ntl[seg];
    const int tg = lane >> 2, tq = lane & 3;
    const int col = cof[seg] + ntile * 8 + tg;
    const int k0  = ci * 16;
    const float* W = Wp[seg];
    const int ld = ldw[seg], kb = kwb[seg], KR = kre[seg];

    const float wA = (k0 + 2*tq     < KR) ? W[(size_t)(kb + k0 + 2*tq    ) * ld + col] : 0.f;
    const float wB = (k0 + 2*tq + 1 < KR) ? W[(size_t)(kb + k0 + 2*tq + 1) * ld + col] : 0.f;
    const float wC = (k0 + 8 + 2*tq     < KR) ? W[(size_t)(kb + k0 + 8 + 2*tq    ) * ld + col] : 0.f;
    const float wD = (k0 + 8 + 2*tq + 1 < KR) ? W[(size_t)(kb + k0 + 8 + 2*tq + 1) * ld + col] : 0.f;
    bf16 hA,lA,hB,lB,hC,lC,hD,lD;
    bsplit(wA,hA,lA); bsplit(wB,hB,lB); bsplit(wC,hC,lC); bsplit(wD,hD,lD);

    if (is3[seg]) {
        u32* p = g_wscr + off[seg] + ci * (ntl[seg] * 128) + ntile * 128 + lane * 4;
        p[0] = pack2(hA,hB); p[1] = pack2(hC,hD);
        p[2] = pack2(lA,lB); p[3] = pack2(lC,lD);
    } else {
        u32* p = g_wscr + off[seg] + ci * (ntl[seg] * 64) + ntile * 64 + lane * 2;
        p[0] = pack2(hA,hB); p[1] = pack2(hC,hD);
    }
}

// frag uint4 index for (ci, mgroup, mt) + lane
__device__ __forceinline__ int frag_u4(int ci, int mg, int mt, int lane) {
    return ((ci * 2 + mg) * 2 + mt) * 32 + lane;
}

// =====================================================================
// bf16x3 accumulation, A from FRAG layout. Warp tile 32(M) x 64(N).
// =====================================================================
__device__ __forceinline__ void accum3x_frag(
    float acc[2][8][4], const u32* __restrict__ segp, int nch,
    const uint4* __restrict__ fhi, const uint4* __restrict__ flo,
    int mg, int n0, int lane)
{
    const uint4* wb = reinterpret_cast<const uint4*>(segp) + (n0 >> 3) * 32 + lane;
    #pragma unroll 2
    for (int ci = 0; ci < nch; ci++) {
        const uint4* pc = wb + ci * 1024;
        const uint4 AH0 = fhi[frag_u4(ci, mg, 0, lane)];
        const uint4 AH1 = fhi[frag_u4(ci, mg, 1, lane)];
        const uint4 AL0 = flo[frag_u4(ci, mg, 0, lane)];
        const uint4 AL1 = flo[frag_u4(ci, mg, 1, lane)];
        const u32 ah[2][4] = {{AH0.x, AH0.y, AH0.z, AH0.w},
                              {AH1.x, AH1.y, AH1.z, AH1.w}};
        const u32 al[2][4] = {{AL0.x, AL0.y, AL0.z, AL0.w},
                              {AL1.x, AL1.y, AL1.z, AL1.w}};
        #pragma unroll
        for (int np = 0; np < 4; np++) {
            const uint4 Ba = __ldg(pc + (2 * np)     * 32);
            const uint4 Bb = __ldg(pc + (2 * np + 1) * 32);
            const u32 bhA[2] = {Ba.x, Ba.y}, blA[2] = {Ba.z, Ba.w};
            const u32 bhB[2] = {Bb.x, Bb.y}, blB[2] = {Bb.z, Bb.w};
            float* a00 = acc[0][2 * np];
            float* a10 = acc[1][2 * np];
            float* a01 = acc[0][2 * np + 1];
            float* a11 = acc[1][2 * np + 1];
            mma16(a00, al[0], bhA); mma16(a10, al[1], bhA);
            mma16(a01, al[0], bhB); mma16(a11, al[1], bhB);
            mma16(a00, ah[0], blA); mma16(a10, ah[1], blA);
            mma16(a01, ah[0], blB); mma16(a11, ah[1], blB);
            mma16(a00, ah[0], bhA); mma16(a10, ah[1], bhA);
            mma16(a01, ah[0], bhB); mma16(a11, ah[1], bhB);
        }
    }
}

// ---- bf16x3, A from LINEAR layout (e paths: L0, L5e) ----
__device__ __forceinline__ void accum3x_lin(
    float acc[2][8][4], const u32* __restrict__ segp, int nch,
    const bf16* __restrict__ src_hi, const bf16* __restrict__ src_lo,
    int sstr, int mbase, int n0, int tg, int tq, int lane)
{
    const uint4* wb = reinterpret_cast<const uint4*>(segp) + (n0 >> 3) * 32 + lane;
    for (int ci = 0; ci < nch; ci++) {
        const uint4* pc = wb + ci * 1024;
        const int k0 = ci * 16;
        u32 ah[2][4], al[2][4];
        #pragma unroll
        for (int mt = 0; mt < 2; mt++) {
            const int r = mbase + mt * 16 + tg;
            const bf16* ph = src_hi + r * sstr + k0 + 2 * tq;
            const bf16* pl = src_lo + r * sstr + k0 + 2 * tq;
            ah[mt][0] = *(const u32*)(ph);
            ah[mt][1] = *(const u32*)(ph + 8 * sstr);
            ah[mt][2] = *(const u32*)(ph + 8);
            ah[mt][3] = *(const u32*)(ph + 8 * sstr + 8);
            al[mt][0] = *(const u32*)(pl);
            al[mt][1] = *(const u32*)(pl + 8 * sstr);
            al[mt][2] = *(const u32*)(pl + 8);
            al[mt][3] = *(const u32*)(pl + 8 * sstr + 8);
        }
        #pragma unroll
        for (int np = 0; np < 4; np++) {
            const uint4 Ba = __ldg(pc + (2 * np)     * 32);
            const uint4 Bb = __ldg(pc + (2 * np + 1) * 32);
            const u32 bhA[2] = {Ba.x, Ba.y}, blA[2] = {Ba.z, Ba.w};
            const u32 bhB[2] = {Bb.x, Bb.y}, blB[2] = {Bb.z, Bb.w};
            float* a00 = acc[0][2 * np];
            float* a10 = acc[1][2 * np];
            float* a01 = acc[0][2 * np + 1];
            float* a11 = acc[1][2 * np + 1];
            mma16(a00, al[0], bhA); mma16(a10, al[1], bhA);
            mma16(a01, al[0], bhB); mma16(a11, al[1], bhB);
            mma16(a00, ah[0], blA); mma16(a10, ah[1], blA);
            mma16(a01, ah[0], blB); mma16(a11, ah[1], blB);
            mma16(a00, ah[0], bhA); mma16(a10, ah[1], bhA);
            mma16(a01, ah[0], bhB); mma16(a11, ah[1], bhB);
        }
    }
}

// ---- single-pass bf16, 256 cols, A from frag-hi (L7) ----
__device__ __forceinline__ void accum1x_frag256(
    float acc[2][8][4], const u32* __restrict__ segp, int nch,
    const uint4* __restrict__ fhi, int mg, int n0, int lane)
{
    const uint2* wb = reinterpret_cast<const uint2*>(segp) + (n0 >> 3) * 32 + lane;
    #pragma unroll 2
    for (int ci = 0; ci < nch; ci++) {
        const uint2* pc = wb + ci * 1024;
        const uint4 AH0 = fhi[frag_u4(ci, mg, 0, lane)];
        const uint4 AH1 = fhi[frag_u4(ci, mg, 1, lane)];
        const u32 ah[2][4] = {{AH0.x, AH0.y, AH0.z, AH0.w},
                              {AH1.x, AH1.y, AH1.z, AH1.w}};
        #pragma unroll
        for (int np = 0; np < 4; np++) {
            const uint2 Ba = __ldg(pc + (2 * np)     * 32);
            const uint2 Bb = __ldg(pc + (2 * np + 1) * 32);
            const u32 bA[2] = {Ba.x, Ba.y};
            const u32 bB[2] = {Bb.x, Bb.y};
            mma16(acc[0][2 * np],     ah[0], bA);
            mma16(acc[1][2 * np],     ah[1], bA);
            mma16(acc[0][2 * np + 1], ah[0], bB);
            mma16(acc[1][2 * np + 1], ah[1], bB);
        }
    }
}

// ---- single-pass bf16, 128 cols, A from frag-hi (head h-part) ----
__device__ __forceinline__ void accum1x_frag128(
    float acc[2][4][4], const u32* __restrict__ segp, int nch,
    const uint4* __restrict__ fhi, int mg, int n0, int lane)
{
    const uint2* wb = reinterpret_cast<const uint2*>(segp) + (n0 >> 3) * 32 + lane;
    for (int ci = 0; ci < nch; ci++) {
        const uint2* pc = wb + ci * 512;
        const uint4 AH0 = fhi[frag_u4(ci, mg, 0, lane)];
        const uint4 AH1 = fhi[frag_u4(ci, mg, 1, lane)];
        const u32 ah[2][4] = {{AH0.x, AH0.y, AH0.z, AH0.w},
                              {AH1.x, AH1.y, AH1.z, AH1.w}};
        #pragma unroll
        for (int np = 0; np < 2; np++) {
            const uint2 Ba = __ldg(pc + (2 * np)     * 32);
            const uint2 Bb = __ldg(pc + (2 * np + 1) * 32);
            const u32 bA[2] = {Ba.x, Ba.y};
            const u32 bB[2] = {Bb.x, Bb.y};
            mma16(acc[0][2 * np],     ah[0], bA);
            mma16(acc[1][2 * np],     ah[1], bA);
            mma16(acc[0][2 * np + 1], ah[0], bB);
            mma16(acc[1][2 * np + 1], ah[1], bB);
        }
    }
}

// ---- single-pass bf16, 128 cols, A from LINEAR (head d-part) ----
__device__ __forceinline__ void accum1x_lin128(
    float acc[2][4][4], const u32* __restrict__ segp, int nch,
    const bf16* __restrict__ src_hi, int sstr,
    int mbase, int n0, int tg, int tq, int lane)
{
    const uint2* wb = reinterpret_cast<const uint2*>(segp) + (n0 >> 3) * 32 + lane;
    for (int ci = 0; ci < nch; ci++) {
        const uint2* pc = wb + ci * 512;
        const int k0 = ci * 16;
        u32 ah[2][4];
        #pragma unroll
        for (int mt = 0; mt < 2; mt++) {
            const int r = mbase + mt * 16 + tg;
            const bf16* ph = src_hi + r * sstr + k0 + 2 * tq;
            ah[mt][0] = *(const u32*)(ph);
            ah[mt][1] = *(const u32*)(ph + 8 * sstr);
            ah[mt][2] = *(const u32*)(ph + 8);
            ah[mt][3] = *(const u32*)(ph + 8 * sstr + 8);
        }
        #pragma unroll
        for (int np = 0; np < 2; np++) {
            const uint2 Ba = __ldg(pc + (2 * np)     * 32);
            const uint2 Bb = __ldg(pc + (2 * np + 1) * 32);
            const u32 bA[2] = {Ba.x, Ba.y};
            const u32 bB[2] = {Bb.x, Bb.y};
            mma16(acc[0][2 * np],     ah[0], bA);
            mma16(acc[1][2 * np],     ah[1], bA);
            mma16(acc[0][2 * np + 1], ah[0], bB);
            mma16(acc[1][2 * np + 1], ah[1], bB);
        }
    }
}

// ---- Trunk epilogue: bias + optional ReLU, write FRAG hi(+lo).
//      sync_id: -1 = full CTA barrier, >0 = named barrier over this
//      mg-group's 128 threads (valid for layers whose reads/writes stay
//      within the mg group: L0..L5). ----
__device__ __forceinline__ void epilogue_frag(
    float acc[2][8][4], const float* __restrict__ bg, int co,
    u32* __restrict__ fhi, u32* __restrict__ flo, bool relu, bool write_lo,
    int mg, int wq, int n0, int tq, int lane, int sync_id)
{
    barrier_sync(sync_id);
    #pragma unroll
    for (int nt = 0; nt < 8; nt++) {
        const int c = n0 + nt * 8 + 2 * tq;
        const float b0v = bg[co + c];
        const float b1v = bg[co + c + 1];
        const int ci = wq * 4 + (nt >> 1);
        #pragma unroll
        for (int mt = 0; mt < 2; mt++) {
            float v0 = acc[mt][nt][0] + b0v;
            float v1 = acc[mt][nt][1] + b1v;
            float v2 = acc[mt][nt][2] + b0v;
            float v3 = acc[mt][nt][3] + b1v;
            if (relu) {
                v0 = fmaxf(v0, 0.f); v1 = fmaxf(v1, 0.f);
                v2 = fmaxf(v2, 0.f); v3 = fmaxf(v3, 0.f);
            }
            const int ub = (((ci * 2 + mg) * 2 + mt) * 128) + lane * 4 + (nt & 1) * 2;
            bf16 h0, l0, h1, l1, h2, l2, h3, l3;
            bsplit(v0, h0, l0); bsplit(v1, h1, l1);
            bsplit(v2, h2, l2); bsplit(v3, h3, l3);
            fhi[ub + 0] = pack2(h0, h1);
            fhi[ub + 1] = pack2(h2, h3);
            if (write_lo) {
                flo[ub + 0] = pack2(l0, l1);
                flo[ub + 1] = pack2(l2, l3);
            }
        }
    }
    barrier_sync(sync_id);
}

// ---- Head epilogue: bias + ReLU, write fp32 LINEAR (stride HOSTR) ----
__device__ __forceinline__ void epilogue_head(
    float acc[2][4][4], const float* __restrict__ bg,
    float* __restrict__ hout, int mbase, int n0, int tg, int tq)
{
    __syncthreads();
    #pragma unroll
    for (int nt = 0; nt < 4; nt++) {
        const int c = n0 + nt * 8 + 2 * tq;
        const float b0v = bg[c];
        const float b1v = bg[c + 1];
        #pragma unroll
        for (int mt = 0; mt < 2; mt++) {
            const int r = mbase + mt * 16 + tg;
            hout[r * HOSTR + c]           = fmaxf(acc[mt][nt][0] + b0v, 0.f);
            hout[r * HOSTR + c + 1]       = fmaxf(acc[mt][nt][1] + b1v, 0.f);
            hout[(r + 8) * HOSTR + c]     = fmaxf(acc[mt][nt][2] + b0v, 0.f);
            hout[(r + 8) * HOSTR + c + 1] = fmaxf(acc[mt][nt][3] + b1v, 0.f);
        }
    }
    __syncthreads();
}

__device__ __forceinline__ void zero_acc8(float acc[2][8][4]) {
    #pragma unroll
    for (int i = 0; i < 2; i++)
        #pragma unroll
        for (int j = 0; j < 8; j++)
            #pragma unroll
            for (int k = 0; k < 4; k++) acc[i][j][k] = 0.f;
}

__global__ void __launch_bounds__(NRF_THREADS, 2) nerf_tc_kernel(
    const float* __restrict__ pts, const float* __restrict__ dirs,
    const float* __restrict__ b0, const float* __restrict__ b1,
    const float* __restrict__ b2, const float* __restrict__ b3,
    const float* __restrict__ b4, const float* __restrict__ b5,
    const float* __restrict__ b6, const float* __restrict__ b7,
    const float* __restrict__ W7, const float* __restrict__ bc,
    const float* __restrict__ Wo, const float* __restrict__ bo,
    float* __restrict__ out_color, float* __restrict__ out_sigma, int P)
{
    extern __shared__ char smc[];
    u32*  fhi  = (u32*)smc;                          // 32768 B frag hi
    u32*  flo  = fhi + FRAG_U32S;                    // 33024 B union: frag lo / head fp32
    float* hout = (float*)flo;                       // aliases flo (flo dead post-L7)
    bf16* e_hi = (bf16*)(smc + 32768 + 33024);       // [64][ESB]
    bf16* e_lo = e_hi + NRF_TILE * ESB;

    const int tid  = threadIdx.x;
    const int warp = tid >> 5;
    const int lane = tid & 31;
    const int tg = lane >> 2;
    const int tq = lane & 3;
    const int mg = warp >> 2;
    const int wq = warp & 3;
    const int mbase  = mg * 32;
    const int n0_256 = wq * 64;
    const int n0_128 = wq * 32;
    const int base = blockIdx.x * NRF_TILE;
    const int mg_bar = mg + 1;                       // named barrier id (1 or 2)
    const uint4* fhi4 = reinterpret_cast<const uint4*>(fhi);
    const uint4* flo4 = reinterpret_cast<const uint4*>(flo);

    // ---- xyz harmonic embedding, linear pre-split hi/lo ----
    if (tid < NRF_TILE) {
        const int n = base + tid;
        const float x = pts[n * 3 + 0];
        const float y = pts[n * 3 + 1];
        const float z = pts[n * 3 + 2];
        bf16* eh = e_hi + tid * ESB;
        bf16* el = e_lo + tid * ESB;
        #pragma unroll
        for (int h = 0; h < 6; h++) {
            const float f = (float)(1 << h);
            float sx, cx, sy, cy, sz, cz;
            sincosf(x * f, &sx, &cx);
            sincosf(y * f, &sy, &cy);
            sincosf(z * f, &sz, &cz);
            bf16 hh, ll;
            bsplit(sx, hh, ll); eh[0  + h] = hh; el[0  + h] = ll;
            bsplit(sy, hh, ll); eh[6  + h] = hh; el[6  + h] = ll;
            bsplit(sz, hh, ll); eh[12 + h] = hh; el[12 + h] = ll;
            bsplit(cx, hh, ll); eh[18 + h] = hh; el[18 + h] = ll;
            bsplit(cy, hh, ll); eh[24 + h] = hh; el[24 + h] = ll;
            bsplit(cz, hh, ll); eh[30 + h] = hh; el[30 + h] = ll;
        }
        bf16 hh, ll;
        bsplit(x, hh, ll); eh[36] = hh; el[36] = ll;
        bsplit(y, hh, ll); eh[37] = hh; el[37] = ll;
        bsplit(z, hh, ll); eh[38] = hh; el[38] = ll;
        const bf16 zb = __float2bfloat16_rn(0.f);
        #pragma unroll
        for (int c = 39; c < 48; c++) { eh[c] = zb; el[c] = zb; }
    }
    __syncthreads();   // e visible to all warps (L0/L5 read it)

    float acc[2][8][4];

    // ---- L0: e(39) -> 256, ReLU (linear A) — named barrier ----
    zero_acc8(acc);
    accum3x_lin(acc, g_wscr + OFF_W0, 3, e_hi, e_lo, ESB, mbase, n0_256, tg, tq, lane);
    epilogue_frag(acc, b0, 0, fhi, flo, true, true, mg, wq, n0_256, tq, lane, mg_bar);

    // ---- L1..L4 (frag A) — named barriers ----
    {
        const u32* segs[4] = {g_wscr + OFF_W1, g_wscr + OFF_W2,
                              g_wscr + OFF_W3, g_wscr + OFF_W4};
        const float* bs[4] = {b1, b2, b3, b4};
        #pragma unroll 1
        for (int l = 0; l < 4; l++) {
            zero_acc8(acc);
            accum3x_frag(acc, segs[l], 16, fhi4, flo4, mg, n0_256, lane);
            epilogue_frag(acc, bs[l], 0, fhi, flo, true, true, mg, wq, n0_256, tq, lane, mg_bar);
        }
    }

    // ---- L5: [h(frag), e(linear)] — named barrier ----
    zero_acc8(acc);
    accum3x_frag(acc, g_wscr + OFF_W5H, 16, fhi4, flo4, mg, n0_256, lane);
    accum3x_lin(acc, g_wscr + OFF_W5E, 3, e_hi, e_lo, ESB, mbase, n0_256, tg, tq, lane);
    epilogue_frag(acc, b5, 0, fhi, flo, true, true, mg, wq, n0_256, tq, lane, mg_bar);

    // ---- L6 (frag A) — FULL barriers (sigma below reads across mg) ----
    zero_acc8(acc);
    accum3x_frag(acc, g_wscr + OFF_W6, 16, fhi4, flo4, mg, n0_256, lane);
    epilogue_frag(acc, b6, 0, fhi, flo, true, true, mg, wq, n0_256, tq, lane, -1);

    // ---- Sigma: fp32 dot over h6 read from frag layout (cross-mg reads) ----
    if (tid < NRF_TILE) {
        const int row = tid;
        const int smg = row >> 5, smt = (row >> 4) & 1;
        const int shseg = (row >> 3) & 1, stg = row & 7;
        float s = b7[0];
        #pragma unroll 4
        for (int k = 0; k < 256; k += 2) {
            const int cp = k >> 1;
            const int ci = cp >> 3, cq = cp & 7;
            const int half = cq >> 2, tqd = cq & 3;
            const int idx = ((ci * 2 + smg) * 2 + smt) * 128
                          + (stg * 4 + tqd) * 4 + half * 2 + shseg;
            const u32 uh = fhi[idx];
            const u32 ul = flo[idx];
            s = fmaf(bf_lo(uh) + bf_lo(ul), W7[(size_t)k * 257], s);
            s = fmaf(bf_hi(uh) + bf_hi(ul), W7[(size_t)(k + 1) * 257], s);
        }
        out_sigma[base + tid] = fmaxf(s, 0.f);
    }

    // ---- L7 cols 1..256 (1x, frag-hi A) — FULL barriers (sigma WAR) ----
    zero_acc8(acc);
    accum1x_frag256(acc, g_wscr + OFF_W7, 16, fhi4, mg, n0_256, lane);
    epilogue_frag(acc, b7, 1, fhi, flo, false, false, mg, wq, n0_256, tq, lane, -1);

    // ---- dir harmonic embedding into e_hi (linear) ----
    if (tid < NRF_TILE) {
        const int n = base + tid;
        const int r = n / P;
        const float dx = dirs[r * 3 + 0];
        const float dy = dirs[r * 3 + 1];
        const float dz = dirs[r * 3 + 2];
        bf16* eh = e_hi + tid * ESB;
        #pragma unroll
        for (int h = 0; h < 4; h++) {
            const float f = (float)(1 << h);
            float sx, cx, sy, cy, sz, cz;
            sincosf(dx * f, &sx, &cx);
            sincosf(dy * f, &sy, &cy);
            sincosf(dz * f, &sz, &cz);
            eh[0  + h] = __float2bfloat16_rn(sx);
            eh[4  + h] = __float2bfloat16_rn(sy);
            eh[8  + h] = __float2bfloat16_rn(sz);
            eh[12 + h] = __float2bfloat16_rn(cx);
            eh[16 + h] = __float2bfloat16_rn(cy);
            eh[20 + h] = __float2bfloat16_rn(cz);
        }
        eh[24] = __float2bfloat16_rn(dx);
        eh[25] = __float2bfloat16_rn(dy);
        eh[26] = __float2bfloat16_rn(dz);
        const bf16 zb = __float2bfloat16_rn(0.f);
        #pragma unroll
        for (int c = 27; c < 32; c++) eh[c] = zb;
    }
    __syncthreads();

    // ---- Color head: [h7(frag-hi), d(linear)] -> 128, ReLU, fp32 out ----
    {
        float acc2[2][4][4];
        #pragma unroll
        for (int i = 0; i < 2; i++)
            #pragma unroll
            for (int j = 0; j < 4; j++)
                #pragma unroll
                for (int k = 0; k < 4; k++) acc2[i][j][k] = 0.f;
        accum1x_frag128(acc2, g_wscr + OFF_WCH, 16, fhi4, mg, n0_128, lane);
        accum1x_lin128(acc2, g_wscr + OFF_WCE, 2, e_hi, ESB, mbase, n0_128, tg, tq, lane);
        epilogue_head(acc2, bc, hout, mbase, n0_128, tg, tq);
    }

    // ---- Output: sigmoid(hout @ Wo + bo), 192 (point,channel) pairs ----
    if (tid < NRF_TILE * 3) {
        const int p = tid / 3;
        const int c = tid - p * 3;
        float s = bo[c];
        const float* hp = hout + p * HOSTR;
        #pragma unroll 4
        for (int k = 0; k < 128; k++)
            s = fmaf(hp[k], Wo[k * 3 + c], s);
        out_color[(base + p) * 3 + c] = 1.f / (1.f + expf(-s));
    }
}

extern "C" void kernel_launch(void* const* d_in, const int* in_sizes, int n_in,
                              void* d_out, int out_size)
{
    const float* pts  = (const float*)d_in[0];
    const float* dirs = (const float*)d_in[1];
    const float* W0 = (const float*)d_in[2];   const float* b0 = (const float*)d_in[3];
    const float* W1 = (const float*)d_in[4];   const float* b1 = (const float*)d_in[5];
    const float* W2 = (const float*)d_in[6];   const float* b2 = (const float*)d_in[7];
    const float* W3 = (const float*)d_in[8];   const float* b3 = (const float*)d_in[9];
    const float* W4 = (const float*)d_in[10];  const float* b4 = (const float*)d_in[11];
    const float* W5 = (const float*)d_in[12];  const float* b5 = (const float*)d_in[13];
    const float* W6 = (const float*)d_in[14];  const float* b6 = (const float*)d_in[15];
    const float* W7 = (const float*)d_in[16];  const float* b7 = (const float*)d_in[17];
    const float* Wc = (const float*)d_in[18];  const float* bc = (const float*)d_in[19];
    const float* Wo = (const float*)d_in[20];  const float* bo = (const float*)d_in[21];

    const int N = in_sizes[0] / 3;        // 131072 points
    const int R = in_sizes[1] / 3;        // 2048 rays
    const int P = N / R;                  // 64 samples per ray

    float* out_color = (float*)d_out;               // [N,3] first (tuple order)
    float* out_sigma = out_color + (size_t)N * 3;   // [N,1] after

    prep_weights<<<(PREP_ELEMS + 255) / 256, 256>>>(
        W0, W1, W2, W3, W4, W5, W6, W7, Wc);

    const int smem_bytes = 32768 + 33024 + 2 * (NRF_TILE * ESB * (int)sizeof(bf16));
    cudaFuncSetAttribute(nerf_tc_kernel,
                         cudaFuncAttributeMaxDynamicSharedMemorySize, smem_bytes);

    nerf_tc_kernel<<<N / NRF_TILE, NRF_THREADS, smem_bytes>>>(
        pts, dirs,
        b0, b1, b2, b3, b4, b5, b6, b7,
        W7, bc, Wo, bo,
        out_color, out_sigma, P);
}